// round 2
// baseline (speedup 1.0000x reference)
#include <cuda_runtime.h>
#include <cuda_bf16.h>
#include <math.h>

#define NN 50000
#define NE 800000
#define EP (NE + NN)   // edges + self loops
#define FD 128

typedef unsigned long long ull;

// -------------------- device scratch (no allocs allowed) --------------------
__device__ float g_Q[NN * FD];
__device__ float g_K[NN * FD];
__device__ float g_V[NN * FD];
__device__ int   g_cnt[NN];
__device__ int   g_off[NN + 1];
__device__ int   g_cur[NN];
__device__ int   g_scol[EP];

// -------------------- packed f32x2 helpers --------------------
__device__ __forceinline__ ull ffma2(ull a, ull b, ull c) {
    ull d; asm("fma.rn.f32x2 %0, %1, %2, %3;" : "=l"(d) : "l"(a), "l"(b), "l"(c)); return d;
}
__device__ __forceinline__ float2 unpack2(ull v) {
    float2 r; asm("mov.b64 {%0, %1}, %2;" : "=f"(r.x), "=f"(r.y) : "l"(v)); return r;
}

// -------------------- GEMM: C = x @ W (+bias, relu optional) --------------------
// 128x128 tile, BK=8, 256 threads, 8x8 per thread.
// f32x2 lanes hold TWO ROWS of the same column:
//   x row-pairs come packed directly from LDS.64 of xs[k][row]
//   weights are stored duplicated (w,w) in shared -> LDS.128 gives packed bcast
// => zero pack movs in the inner loop.
__global__ __launch_bounds__(256, 2) void gemm_qkv_kernel(
    const float* __restrict__ x,
    const float* __restrict__ Wq, const float* __restrict__ bq,
    const float* __restrict__ Wk, const float* __restrict__ bk,
    const float* __restrict__ Wv)
{
    const int mat = blockIdx.y;
    const float* __restrict__ W = (mat == 0) ? Wq : ((mat == 1) ? Wk : Wv);
    const float* __restrict__ B = (mat == 0) ? bq : ((mat == 1) ? bk : nullptr);
    float* __restrict__ C = (mat == 0) ? g_Q : ((mat == 1) ? g_K : g_V);
    const bool dorelu = (mat < 2);

    __shared__ float  xs[8][132];    // [k][row], padded vs bank conflicts
    __shared__ float2 ws2[8][128];   // [k][col] duplicated (w,w)

    const int t  = threadIdx.x;
    const int tx = t & 15;           // col group: cols tx*8 .. tx*8+7
    const int ty = t >> 4;           // row group: rows ty*8 .. ty*8+7
    const int row0 = blockIdx.x * 128;

    ull acc[4][8];
#pragma unroll
    for (int i = 0; i < 4; i++)
#pragma unroll
        for (int j = 0; j < 8; j++) acc[i][j] = 0ull;

    for (int k0 = 0; k0 < FD; k0 += 8) {
        // x tile: 128 rows x 8 k.  thread -> row t>>1, k-quad (t&1)*4
        {
            int r   = t >> 1;
            int kk4 = (t & 1) * 4;
            float4 v = make_float4(0.f, 0.f, 0.f, 0.f);
            if (row0 + r < NN)
                v = *(const float4*)(x + (size_t)(row0 + r) * FD + k0 + kk4);
            xs[kk4 + 0][r] = v.x;
            xs[kk4 + 1][r] = v.y;
            xs[kk4 + 2][r] = v.z;
            xs[kk4 + 3][r] = v.w;
        }
        // W tile duplicated: 8 k x 128 cols
        {
            int kk = t >> 5;
            int n4 = (t & 31) * 4;
            float4 w = *(const float4*)(W + (size_t)(k0 + kk) * FD + n4);
            ws2[kk][n4 + 0] = make_float2(w.x, w.x);
            ws2[kk][n4 + 1] = make_float2(w.y, w.y);
            ws2[kk][n4 + 2] = make_float2(w.z, w.z);
            ws2[kk][n4 + 3] = make_float2(w.w, w.w);
        }
        __syncthreads();

#pragma unroll
        for (int kk = 0; kk < 8; kk++) {
            ull xp[4];
#pragma unroll
            for (int i = 0; i < 4; i++)
                xp[i] = *(const ull*)&xs[kk][ty * 8 + 2 * i];   // packed (row, row+1)
            ull wd[8];
#pragma unroll
            for (int j = 0; j < 4; j++) {
                ulonglong2 wv = *(const ulonglong2*)&ws2[kk][tx * 8 + 2 * j];
                wd[2 * j]     = wv.x;                            // packed (w, w)
                wd[2 * j + 1] = wv.y;
            }
#pragma unroll
            for (int i = 0; i < 4; i++)
#pragma unroll
                for (int j = 0; j < 8; j++)
                    acc[i][j] = ffma2(xp[i], wd[j], acc[i][j]);
        }
        __syncthreads();
    }

    float bb[8];
#pragma unroll
    for (int j = 0; j < 8; j++) bb[j] = 0.f;
    if (B) {
        float4 b0 = *(const float4*)(B + tx * 8);
        float4 b1 = *(const float4*)(B + tx * 8 + 4);
        bb[0] = b0.x; bb[1] = b0.y; bb[2] = b0.z; bb[3] = b0.w;
        bb[4] = b1.x; bb[5] = b1.y; bb[6] = b1.z; bb[7] = b1.w;
    }

#pragma unroll
    for (int i = 0; i < 4; i++) {
        int r0 = row0 + ty * 8 + 2 * i;
        float o0[8], o1[8];
#pragma unroll
        for (int j = 0; j < 8; j++) {
            float2 p = unpack2(acc[i][j]);
            float a = p.x + bb[j];
            float b = p.y + bb[j];
            if (dorelu) { a = fmaxf(a, 0.f); b = fmaxf(b, 0.f); }
            o0[j] = a; o1[j] = b;
        }
        if (r0 < NN) {
            *(float4*)(C + (size_t)r0 * FD + tx * 8)     = make_float4(o0[0], o0[1], o0[2], o0[3]);
            *(float4*)(C + (size_t)r0 * FD + tx * 8 + 4) = make_float4(o0[4], o0[5], o0[6], o0[7]);
        }
        if (r0 + 1 < NN) {
            *(float4*)(C + (size_t)(r0 + 1) * FD + tx * 8)     = make_float4(o1[0], o1[1], o1[2], o1[3]);
            *(float4*)(C + (size_t)(r0 + 1) * FD + tx * 8 + 4) = make_float4(o1[4], o1[5], o1[6], o1[7]);
        }
    }
}

// -------------------- counting sort of edges by target node --------------------
__global__ void init_cnt_kernel() {
    int i = blockIdx.x * blockDim.x + threadIdx.x;
    if (i < NN) g_cnt[i] = 1;   // self loop pre-counted
}

__global__ void hist_kernel(const int* __restrict__ ei) {
    int e = blockIdx.x * blockDim.x + threadIdx.x;
    if (e < NE) atomicAdd(&g_cnt[ei[e]], 1);   // row = target = ei[0][e]
}

// single-block exclusive scan over g_cnt -> g_off (and g_cur copy)
__global__ __launch_bounds__(1024) void scan_kernel() {
    __shared__ int sums[1024];
    const int t = threadIdx.x;
    const int CH = (NN + 1023) / 1024;   // 49
    int start = t * CH;
    int end   = start + CH; if (end > NN) end = NN;

    int s = 0;
    for (int i = start; i < end; i++) s += g_cnt[i];
    sums[t] = s;
    __syncthreads();
    for (int d = 1; d < 1024; d <<= 1) {
        int v = (t >= d) ? sums[t - d] : 0;
        __syncthreads();
        sums[t] += v;
        __syncthreads();
    }
    int run = sums[t] - s;   // exclusive prefix for this thread's chunk
    for (int i = start; i < end; i++) {
        g_off[i] = run;
        g_cur[i] = run;
        run += g_cnt[i];
    }
    if (start < NN && end == NN) g_off[NN] = run;
}

__global__ void scatter_kernel(const int* __restrict__ ei) {
    int e = blockIdx.x * blockDim.x + threadIdx.x;
    if (e >= EP) return;
    int r, c;
    if (e < NE) { r = ei[e]; c = ei[NE + e]; }
    else        { r = e - NE; c = r; }          // self loop
    int pos = atomicAdd(&g_cur[r], 1);
    g_scol[pos] = c;
}

// -------------------- fused attention + aggregation --------------------
// One warp per target node, online softmax, 2 edges per iteration so that
// 4 independent 16B loads are in flight and one rescale covers both edges.
__global__ __launch_bounds__(256) void aggregate_kernel(
    const float* __restrict__ bias, float* __restrict__ out)
{
    const int warp = (blockIdx.x * blockDim.x + threadIdx.x) >> 5;
    const int lane = threadIdx.x & 31;
    if (warp >= NN) return;
    const int n = warp;

    const float4 q = *(const float4*)(g_Q + (size_t)n * FD + lane * 4);

    const int beg = g_off[n];
    const int end = g_off[n + 1];

    float m = -INFINITY;
    float s = 0.f;
    float4 acc = make_float4(0.f, 0.f, 0.f, 0.f);

    int e = beg;
    for (; e + 2 <= end; e += 2) {
        int c0 = g_scol[e];
        int c1 = g_scol[e + 1];
        const float4 k0 = *(const float4*)(g_K + (size_t)c0 * FD + lane * 4);
        const float4 k1 = *(const float4*)(g_K + (size_t)c1 * FD + lane * 4);
        const float4 v0 = *(const float4*)(g_V + (size_t)c0 * FD + lane * 4);
        const float4 v1 = *(const float4*)(g_V + (size_t)c1 * FD + lane * 4);

        float t0 = q.x * k0.x + q.y * k0.y + q.z * k0.z + q.w * k0.w;
        float t1 = q.x * k1.x + q.y * k1.y + q.z * k1.z + q.w * k1.w;
        t0 += __shfl_xor_sync(0xffffffffu, t0, 1);
        t1 += __shfl_xor_sync(0xffffffffu, t1, 1);
        t0 += __shfl_xor_sync(0xffffffffu, t0, 2);
        t1 += __shfl_xor_sync(0xffffffffu, t1, 2);

        float nm = fmaxf(m, fmaxf(t0, t1));
        float f  = __expf(m - nm);        // first iter: exp(-inf) = 0
        float w0 = __expf(t0 - nm);
        float w1 = __expf(t1 - nm);
        s = s * f + w0 + w1;
        acc.x = acc.x * f + w0 * v0.x + w1 * v1.x;
        acc.y = acc.y * f + w0 * v0.y + w1 * v1.y;
        acc.z = acc.z * f + w0 * v0.z + w1 * v1.z;
        acc.w = acc.w * f + w0 * v0.w + w1 * v1.w;
        m = nm;
    }
    if (e < end) {
        int c0 = g_scol[e];
        const float4 k0 = *(const float4*)(g_K + (size_t)c0 * FD + lane * 4);
        const float4 v0 = *(const float4*)(g_V + (size_t)c0 * FD + lane * 4);
        float t0 = q.x * k0.x + q.y * k0.y + q.z * k0.z + q.w * k0.w;
        t0 += __shfl_xor_sync(0xffffffffu, t0, 1);
        t0 += __shfl_xor_sync(0xffffffffu, t0, 2);
        float nm = fmaxf(m, t0);
        float f  = __expf(m - nm);
        float w0 = __expf(t0 - nm);
        s = s * f + w0;
        acc.x = acc.x * f + w0 * v0.x;
        acc.y = acc.y * f + w0 * v0.y;
        acc.z = acc.z * f + w0 * v0.z;
        acc.w = acc.w * f + w0 * v0.w;
    }

    const float inv = 1.f / s;
    const float4 b4 = *(const float4*)(bias + lane * 4);
    float4 o = make_float4(acc.x * inv + b4.x, acc.y * inv + b4.y,
                           acc.z * inv + b4.z, acc.w * inv + b4.w);
    *(float4*)(out + (size_t)n * FD + lane * 4) = o;
}

// -------------------- launch --------------------
extern "C" void kernel_launch(void* const* d_in, const int* in_sizes, int n_in,
                              void* d_out, int out_size)
{
    const float* x  = (const float*)d_in[0];
    const int*   ei = (const int*)d_in[1];
    const float* Wq = (const float*)d_in[2];
    const float* bq = (const float*)d_in[3];
    const float* Wk = (const float*)d_in[4];
    const float* bk = (const float*)d_in[5];
    const float* Wv = (const float*)d_in[6];
    const float* bo = (const float*)d_in[7];
    float* out = (float*)d_out;

    // edge sort chain
    init_cnt_kernel<<<(NN + 255) / 256, 256>>>();
    hist_kernel<<<(NE + 255) / 256, 256>>>(ei);
    scan_kernel<<<1, 1024>>>();
    scatter_kernel<<<(EP + 255) / 256, 256>>>(ei);

    // dense Q/K/V
    dim3 ggrid((NN + 127) / 128, 3);
    gemm_qkv_kernel<<<ggrid, 256>>>(x, Wq, bq, Wk, bk, Wv);

    // fused attention + aggregation (1 warp / node)
    aggregate_kernel<<<(NN * 32 + 255) / 256, 256>>>(bo, out);
}

// round 3
// speedup vs baseline: 1.6391x; 1.6391x over previous
#include <cuda_runtime.h>
#include <cuda_bf16.h>
#include <math.h>

#define NN 50000
#define NE 800000
#define EP (NE + NN)   // edges + self loops
#define FD 128

typedef unsigned long long ull;

// -------------------- device scratch (no allocs allowed) --------------------
__device__ float g_Q[NN * FD];
__device__ float g_K[NN * FD];
__device__ float g_V[NN * FD];
__device__ int   g_cnt[NN];
__device__ int   g_off[NN + 1];
__device__ int   g_cur[NN];
__device__ int   g_scol[EP];

// -------------------- packed f32x2 helpers --------------------
__device__ __forceinline__ ull ffma2(ull a, ull b, ull c) {
    ull d; asm("fma.rn.f32x2 %0, %1, %2, %3;" : "=l"(d) : "l"(a), "l"(b), "l"(c)); return d;
}
__device__ __forceinline__ float2 unpack2(ull v) {
    float2 r; asm("mov.b64 {%0, %1}, %2;" : "=f"(r.x), "=f"(r.y) : "l"(v)); return r;
}

// -------------------- GEMM: C = x @ W (+bias, relu optional) --------------------
// 128x128 tile, BK=8, 256 threads, 8 rows x 8 cols per thread.
// f32x2 lanes hold TWO ROWS of one column:
//   x row-pairs packed for free via LDS.64 of xs[k][row]
//   weights duplicated (w,w) in shared; thread tx owns cols {tx+16j} so the
//   LDS.64 of ws2[kk][tx+16j] is conflict-free (banks 2*tx, half-warp bcast).
// No launch_bounds min-blocks clamp -> no spills (acc = 64 regs).
__global__ __launch_bounds__(256) void gemm_qkv_kernel(
    const float* __restrict__ x,
    const float* __restrict__ Wq, const float* __restrict__ bq,
    const float* __restrict__ Wk, const float* __restrict__ bk,
    const float* __restrict__ Wv)
{
    const int mat = blockIdx.y;
    const float* __restrict__ W = (mat == 0) ? Wq : ((mat == 1) ? Wk : Wv);
    const float* __restrict__ B = (mat == 0) ? bq : ((mat == 1) ? bk : nullptr);
    float* __restrict__ C = (mat == 0) ? g_Q : ((mat == 1) ? g_K : g_V);
    const bool dorelu = (mat < 2);

    __shared__ float  xs[8][132];    // [k][row], padded
    __shared__ float2 ws2[8][128];   // [k][col], duplicated (w,w)

    const int t  = threadIdx.x;
    const int tx = t & 15;           // cols tx + 16j
    const int ty = t >> 4;           // rows ty*8 .. ty*8+7
    const int row0 = blockIdx.x * 128;

    ull acc[4][8];
#pragma unroll
    for (int i = 0; i < 4; i++)
#pragma unroll
        for (int j = 0; j < 8; j++) acc[i][j] = 0ull;

    const int lw = t & 31;           // lane-in-warp style index for W staging
    const int kw = t >> 5;           // k row for W staging

    for (int k0 = 0; k0 < FD; k0 += 8) {
        // x tile: 128 rows x 8 k.  thread -> row t>>1, k-quad (t&1)*4
        {
            int r   = t >> 1;
            int kk4 = (t & 1) * 4;
            float4 v = make_float4(0.f, 0.f, 0.f, 0.f);
            if (row0 + r < NN)
                v = *(const float4*)(x + (size_t)(row0 + r) * FD + k0 + kk4);
            xs[kk4 + 0][r] = v.x;
            xs[kk4 + 1][r] = v.y;
            xs[kk4 + 2][r] = v.z;
            xs[kk4 + 3][r] = v.w;
        }
        // W tile duplicated: thread handles cols lw + 32*i of k-row kw.
        // STS.64 banks = 2*lw mod 32 -> exactly 2-phase, no excess conflicts.
        {
            const float* wrow = W + (size_t)(k0 + kw) * FD;
#pragma unroll
            for (int i = 0; i < 4; i++) {
                float w = wrow[lw + 32 * i];
                ws2[kw][lw + 32 * i] = make_float2(w, w);
            }
        }
        __syncthreads();

#pragma unroll
        for (int kk = 0; kk < 8; kk++) {
            ull xp[4];
#pragma unroll
            for (int i = 0; i < 4; i++)
                xp[i] = *(const ull*)&xs[kk][ty * 8 + 2 * i];     // (row, row+1)
            ull wd[8];
#pragma unroll
            for (int j = 0; j < 8; j++)
                wd[j] = *(const ull*)&ws2[kk][tx + 16 * j];       // (w, w)
#pragma unroll
            for (int i = 0; i < 4; i++)
#pragma unroll
                for (int j = 0; j < 8; j++)
                    acc[i][j] = ffma2(xp[i], wd[j], acc[i][j]);
        }
        __syncthreads();
    }

    float bb[8];
#pragma unroll
    for (int j = 0; j < 8; j++) bb[j] = B ? B[tx + 16 * j] : 0.f;

#pragma unroll
    for (int i = 0; i < 4; i++) {
        int r0 = row0 + ty * 8 + 2 * i;
        bool ok0 = (r0 < NN), ok1 = (r0 + 1 < NN);
        float* c0 = C + (size_t)r0 * FD;
        float* c1 = c0 + FD;
#pragma unroll
        for (int j = 0; j < 8; j++) {
            float2 p = unpack2(acc[i][j]);
            float a = p.x + bb[j];
            float b = p.y + bb[j];
            if (dorelu) { a = fmaxf(a, 0.f); b = fmaxf(b, 0.f); }
            int cj = tx + 16 * j;
            if (ok0) c0[cj] = a;
            if (ok1) c1[cj] = b;
        }
    }
}

// -------------------- counting sort of edges by target node --------------------
__global__ void init_cnt_kernel() {
    int i = blockIdx.x * blockDim.x + threadIdx.x;
    if (i < NN) g_cnt[i] = 1;   // self loop pre-counted
}

__global__ void hist_kernel(const int* __restrict__ ei) {
    int e = blockIdx.x * blockDim.x + threadIdx.x;
    if (e < NE) atomicAdd(&g_cnt[ei[e]], 1);   // row = target = ei[0][e]
}

// single-block exclusive scan over g_cnt -> g_off (and g_cur copy)
__global__ __launch_bounds__(1024) void scan_kernel() {
    __shared__ int sums[1024];
    const int t = threadIdx.x;
    const int CH = (NN + 1023) / 1024;   // 49
    int start = t * CH;
    int end   = start + CH; if (end > NN) end = NN;

    int s = 0;
    for (int i = start; i < end; i++) s += g_cnt[i];
    sums[t] = s;
    __syncthreads();
    for (int d = 1; d < 1024; d <<= 1) {
        int v = (t >= d) ? sums[t - d] : 0;
        __syncthreads();
        sums[t] += v;
        __syncthreads();
    }
    int run = sums[t] - s;   // exclusive prefix for this thread's chunk
    for (int i = start; i < end; i++) {
        g_off[i] = run;
        g_cur[i] = run;
        run += g_cnt[i];
    }
    if (start < NN && end == NN) g_off[NN] = run;
}

__global__ void scatter_kernel(const int* __restrict__ ei) {
    int e = blockIdx.x * blockDim.x + threadIdx.x;
    if (e >= EP) return;
    int r, c;
    if (e < NE) { r = ei[e]; c = ei[NE + e]; }
    else        { r = e - NE; c = r; }          // self loop
    int pos = atomicAdd(&g_cur[r], 1);
    g_scol[pos] = c;
}

// -------------------- fused attention + aggregation --------------------
// One warp per target node, online softmax, 2 edges per iteration so that
// 4 independent 16B loads are in flight and one rescale covers both edges.
__global__ __launch_bounds__(256) void aggregate_kernel(
    const float* __restrict__ bias, float* __restrict__ out)
{
    const int warp = (blockIdx.x * blockDim.x + threadIdx.x) >> 5;
    const int lane = threadIdx.x & 31;
    if (warp >= NN) return;
    const int n = warp;

    const float4 q = *(const float4*)(g_Q + (size_t)n * FD + lane * 4);

    const int beg = g_off[n];
    const int end = g_off[n + 1];

    float m = -INFINITY;
    float s = 0.f;
    float4 acc = make_float4(0.f, 0.f, 0.f, 0.f);

    int e = beg;
    for (; e + 2 <= end; e += 2) {
        int c0 = g_scol[e];
        int c1 = g_scol[e + 1];
        const float4 k0 = *(const float4*)(g_K + (size_t)c0 * FD + lane * 4);
        const float4 k1 = *(const float4*)(g_K + (size_t)c1 * FD + lane * 4);
        const float4 v0 = *(const float4*)(g_V + (size_t)c0 * FD + lane * 4);
        const float4 v1 = *(const float4*)(g_V + (size_t)c1 * FD + lane * 4);

        float t0 = q.x * k0.x + q.y * k0.y + q.z * k0.z + q.w * k0.w;
        float t1 = q.x * k1.x + q.y * k1.y + q.z * k1.z + q.w * k1.w;
        t0 += __shfl_xor_sync(0xffffffffu, t0, 1);
        t1 += __shfl_xor_sync(0xffffffffu, t1, 1);
        t0 += __shfl_xor_sync(0xffffffffu, t0, 2);
        t1 += __shfl_xor_sync(0xffffffffu, t1, 2);

        float nm = fmaxf(m, fmaxf(t0, t1));
        float f  = __expf(m - nm);        // first iter: exp(-inf) = 0
        float w0 = __expf(t0 - nm);
        float w1 = __expf(t1 - nm);
        s = s * f + w0 + w1;
        acc.x = acc.x * f + w0 * v0.x + w1 * v1.x;
        acc.y = acc.y * f + w0 * v0.y + w1 * v1.y;
        acc.z = acc.z * f + w0 * v0.z + w1 * v1.z;
        acc.w = acc.w * f + w0 * v0.w + w1 * v1.w;
        m = nm;
    }
    if (e < end) {
        int c0 = g_scol[e];
        const float4 k0 = *(const float4*)(g_K + (size_t)c0 * FD + lane * 4);
        const float4 v0 = *(const float4*)(g_V + (size_t)c0 * FD + lane * 4);
        float t0 = q.x * k0.x + q.y * k0.y + q.z * k0.z + q.w * k0.w;
        t0 += __shfl_xor_sync(0xffffffffu, t0, 1);
        t0 += __shfl_xor_sync(0xffffffffu, t0, 2);
        float nm = fmaxf(m, t0);
        float f  = __expf(m - nm);
        float w0 = __expf(t0 - nm);
        s = s * f + w0;
        acc.x = acc.x * f + w0 * v0.x;
        acc.y = acc.y * f + w0 * v0.y;
        acc.z = acc.z * f + w0 * v0.z;
        acc.w = acc.w * f + w0 * v0.w;
    }

    const float inv = 1.f / s;
    const float4 b4 = *(const float4*)(bias + lane * 4);
    float4 o = make_float4(acc.x * inv + b4.x, acc.y * inv + b4.y,
                           acc.z * inv + b4.z, acc.w * inv + b4.w);
    *(float4*)(out + (size_t)n * FD + lane * 4) = o;
}

// -------------------- launch --------------------
extern "C" void kernel_launch(void* const* d_in, const int* in_sizes, int n_in,
                              void* d_out, int out_size)
{
    const float* x  = (const float*)d_in[0];
    const int*   ei = (const int*)d_in[1];
    const float* Wq = (const float*)d_in[2];
    const float* bq = (const float*)d_in[3];
    const float* Wk = (const float*)d_in[4];
    const float* bk = (const float*)d_in[5];
    const float* Wv = (const float*)d_in[6];
    const float* bo = (const float*)d_in[7];
    float* out = (float*)d_out;

    // edge sort chain
    init_cnt_kernel<<<(NN + 255) / 256, 256>>>();
    hist_kernel<<<(NE + 255) / 256, 256>>>(ei);
    scan_kernel<<<1, 1024>>>();
    scatter_kernel<<<(EP + 255) / 256, 256>>>(ei);

    // dense Q/K/V
    dim3 ggrid((NN + 127) / 128, 3);
    gemm_qkv_kernel<<<ggrid, 256>>>(x, Wq, bq, Wk, bk, Wv);

    // fused attention + aggregation (1 warp / node)
    aggregate_kernel<<<(NN * 32 + 255) / 256, 256>>>(bo, out);
}

// round 4
// speedup vs baseline: 1.6807x; 1.0254x over previous
#include <cuda_runtime.h>
#include <cuda_bf16.h>
#include <math.h>

#define NN 50000
#define NE 800000
#define EP (NE + NN)   // edges + self loops
#define FD 128

#define HIST_BLOCKS ((NE + 255) / 256)   // 3125
#define GEMM_BX     ((NN + 127) / 128)   // 391

typedef unsigned long long ull;

// -------------------- device scratch (no allocs allowed) --------------------
__device__ float g_Q[NN * FD];
__device__ float g_K[NN * FD];
__device__ float g_V[NN * FD];
__device__ int   g_cnt[NN];      // zeroed at module load; re-zeroed by aggregate
__device__ int   g_off[NN + 1];
__device__ int   g_cur[NN];
__device__ int   g_scol[EP];

// -------------------- packed f32x2 helpers --------------------
__device__ __forceinline__ ull ffma2(ull a, ull b, ull c) {
    ull d; asm("fma.rn.f32x2 %0, %1, %2, %3;" : "=l"(d) : "l"(a), "l"(b), "l"(c)); return d;
}
__device__ __forceinline__ float2 unpack2(ull v) {
    float2 r; asm("mov.b64 {%0, %1}, %2;" : "=f"(r.x), "=f"(r.y) : "l"(v)); return r;
}

// -------------------- fused: edge histogram + Q/K/V GEMMs --------------------
// blocks [0, HIST_BLOCKS): histogram of edge targets into g_cnt
// blocks [HIST_BLOCKS, HIST_BLOCKS + 3*GEMM_BX): 128x128-tile GEMM, BK=8,
//   f32x2 row-pair accumulation (see R3 notes: conflict-free duplicated weights).
__global__ __launch_bounds__(256) void fused_gemm_hist_kernel(
    const float* __restrict__ x, const int* __restrict__ ei,
    const float* __restrict__ Wq, const float* __restrict__ bq,
    const float* __restrict__ Wk, const float* __restrict__ bk,
    const float* __restrict__ Wv)
{
    if (blockIdx.x < HIST_BLOCKS) {
        int e = blockIdx.x * 256 + threadIdx.x;
        if (e < NE) atomicAdd(&g_cnt[ei[e]], 1);   // target = ei[0][e]
        return;
    }

    const int bid = blockIdx.x - HIST_BLOCKS;
    const int mat = bid / GEMM_BX;                 // 0: Q, 1: K, 2: V
    const int bx  = bid % GEMM_BX;

    const float* __restrict__ W = (mat == 0) ? Wq : ((mat == 1) ? Wk : Wv);
    const float* __restrict__ B = (mat == 0) ? bq : ((mat == 1) ? bk : nullptr);
    float* __restrict__ C = (mat == 0) ? g_Q : ((mat == 1) ? g_K : g_V);
    const bool dorelu = (mat < 2);

    __shared__ float  xs[8][132];    // [k][row], padded
    __shared__ float2 ws2[8][128];   // [k][col], duplicated (w,w)

    const int t  = threadIdx.x;
    const int tx = t & 15;           // cols tx + 16j
    const int ty = t >> 4;           // rows ty*8 .. ty*8+7
    const int row0 = bx * 128;

    ull acc[4][8];
#pragma unroll
    for (int i = 0; i < 4; i++)
#pragma unroll
        for (int j = 0; j < 8; j++) acc[i][j] = 0ull;

    const int lw = t & 31;
    const int kw = t >> 5;

    for (int k0 = 0; k0 < FD; k0 += 8) {
        {
            int r   = t >> 1;
            int kk4 = (t & 1) * 4;
            float4 v = make_float4(0.f, 0.f, 0.f, 0.f);
            if (row0 + r < NN)
                v = *(const float4*)(x + (size_t)(row0 + r) * FD + k0 + kk4);
            xs[kk4 + 0][r] = v.x;
            xs[kk4 + 1][r] = v.y;
            xs[kk4 + 2][r] = v.z;
            xs[kk4 + 3][r] = v.w;
        }
        {
            const float* wrow = W + (size_t)(k0 + kw) * FD;
#pragma unroll
            for (int i = 0; i < 4; i++) {
                float w = wrow[lw + 32 * i];
                ws2[kw][lw + 32 * i] = make_float2(w, w);
            }
        }
        __syncthreads();

#pragma unroll
        for (int kk = 0; kk < 8; kk++) {
            ull xp[4];
#pragma unroll
            for (int i = 0; i < 4; i++)
                xp[i] = *(const ull*)&xs[kk][ty * 8 + 2 * i];     // (row, row+1)
            ull wd[8];
#pragma unroll
            for (int j = 0; j < 8; j++)
                wd[j] = *(const ull*)&ws2[kk][tx + 16 * j];       // (w, w)
#pragma unroll
            for (int i = 0; i < 4; i++)
#pragma unroll
                for (int j = 0; j < 8; j++)
                    acc[i][j] = ffma2(xp[i], wd[j], acc[i][j]);
        }
        __syncthreads();
    }

    float bb[8];
#pragma unroll
    for (int j = 0; j < 8; j++) bb[j] = B ? B[tx + 16 * j] : 0.f;

#pragma unroll
    for (int i = 0; i < 4; i++) {
        int r0 = row0 + ty * 8 + 2 * i;
        bool ok0 = (r0 < NN), ok1 = (r0 + 1 < NN);
        float* c0 = C + (size_t)r0 * FD;
        float* c1 = c0 + FD;
#pragma unroll
        for (int j = 0; j < 8; j++) {
            float2 p = unpack2(acc[i][j]);
            float a = p.x + bb[j];
            float b = p.y + bb[j];
            if (dorelu) { a = fmaxf(a, 0.f); b = fmaxf(b, 0.f); }
            int cj = tx + 16 * j;
            if (ok0) c0[cj] = a;
            if (ok1) c1[cj] = b;
        }
    }
}

// -------------------- exclusive scan over (g_cnt[i] + 1) --------------------
// the +1 is the implicit self loop; writes g_off / g_cur.
__global__ __launch_bounds__(1024) void scan_kernel() {
    __shared__ int sums[1024];
    const int t = threadIdx.x;
    const int CH = (NN + 1023) / 1024;   // 49
    int start = t * CH;
    int end   = start + CH; if (end > NN) end = NN;

    int s = 0;
    for (int i = start; i < end; i++) s += g_cnt[i] + 1;
    sums[t] = s;
    __syncthreads();
    for (int d = 1; d < 1024; d <<= 1) {
        int v = (t >= d) ? sums[t - d] : 0;
        __syncthreads();
        sums[t] += v;
        __syncthreads();
    }
    int run = sums[t] - s;   // exclusive prefix for this thread's chunk
    for (int i = start; i < end; i++) {
        g_off[i] = run;
        g_cur[i] = run;
        run += g_cnt[i] + 1;
    }
    if (start < NN && end == NN) g_off[NN] = run;
}

__global__ void scatter_kernel(const int* __restrict__ ei) {
    int e = blockIdx.x * blockDim.x + threadIdx.x;
    if (e >= EP) return;
    int r, c;
    if (e < NE) { r = ei[e]; c = ei[NE + e]; }
    else        { r = e - NE; c = r; }          // self loop
    int pos = atomicAdd(&g_cur[r], 1);
    g_scol[pos] = c;
}

// -------------------- fused attention + aggregation --------------------
// One warp per target node, online softmax, 4 edges per iteration:
// 8 independent 16B .nc loads in flight, one rescale per 4 edges.
// Also re-zeros g_cnt for the next graph replay.
__global__ __launch_bounds__(256) void aggregate_kernel(
    const float* __restrict__ bias, float* __restrict__ out)
{
    const int warp = (blockIdx.x * blockDim.x + threadIdx.x) >> 5;
    const int lane = threadIdx.x & 31;
    if (warp >= NN) return;
    const int n = warp;
    if (lane == 0) g_cnt[n] = 0;     // reset for next replay

    const float4 q = __ldg((const float4*)(g_Q + (size_t)n * FD + lane * 4));

    const int beg = g_off[n];
    const int end = g_off[n + 1];

    float m = -INFINITY;
    float s = 0.f;
    float4 acc = make_float4(0.f, 0.f, 0.f, 0.f);

    int e = beg;
    for (; e + 4 <= end; e += 4) {
        int c0 = g_scol[e];
        int c1 = g_scol[e + 1];
        int c2 = g_scol[e + 2];
        int c3 = g_scol[e + 3];
        const float4 k0 = __ldg((const float4*)(g_K + (size_t)c0 * FD + lane * 4));
        const float4 k1 = __ldg((const float4*)(g_K + (size_t)c1 * FD + lane * 4));
        const float4 k2 = __ldg((const float4*)(g_K + (size_t)c2 * FD + lane * 4));
        const float4 k3 = __ldg((const float4*)(g_K + (size_t)c3 * FD + lane * 4));
        const float4 v0 = __ldg((const float4*)(g_V + (size_t)c0 * FD + lane * 4));
        const float4 v1 = __ldg((const float4*)(g_V + (size_t)c1 * FD + lane * 4));
        const float4 v2 = __ldg((const float4*)(g_V + (size_t)c2 * FD + lane * 4));
        const float4 v3 = __ldg((const float4*)(g_V + (size_t)c3 * FD + lane * 4));

        float t0 = q.x * k0.x + q.y * k0.y + q.z * k0.z + q.w * k0.w;
        float t1 = q.x * k1.x + q.y * k1.y + q.z * k1.z + q.w * k1.w;
        float t2 = q.x * k2.x + q.y * k2.y + q.z * k2.z + q.w * k2.w;
        float t3 = q.x * k3.x + q.y * k3.y + q.z * k3.z + q.w * k3.w;
        t0 += __shfl_xor_sync(0xffffffffu, t0, 1);
        t1 += __shfl_xor_sync(0xffffffffu, t1, 1);
        t2 += __shfl_xor_sync(0xffffffffu, t2, 1);
        t3 += __shfl_xor_sync(0xffffffffu, t3, 1);
        t0 += __shfl_xor_sync(0xffffffffu, t0, 2);
        t1 += __shfl_xor_sync(0xffffffffu, t1, 2);
        t2 += __shfl_xor_sync(0xffffffffu, t2, 2);
        t3 += __shfl_xor_sync(0xffffffffu, t3, 2);

        float nm = fmaxf(fmaxf(m, fmaxf(t0, t1)), fmaxf(t2, t3));
        float f  = __expf(m - nm);        // first iter: exp(-inf) = 0
        float w0 = __expf(t0 - nm);
        float w1 = __expf(t1 - nm);
        float w2 = __expf(t2 - nm);
        float w3 = __expf(t3 - nm);
        s = s * f + ((w0 + w1) + (w2 + w3));
        acc.x = acc.x * f + ((w0 * v0.x + w1 * v1.x) + (w2 * v2.x + w3 * v3.x));
        acc.y = acc.y * f + ((w0 * v0.y + w1 * v1.y) + (w2 * v2.y + w3 * v3.y));
        acc.z = acc.z * f + ((w0 * v0.z + w1 * v1.z) + (w2 * v2.z + w3 * v3.z));
        acc.w = acc.w * f + ((w0 * v0.w + w1 * v1.w) + (w2 * v2.w + w3 * v3.w));
        m = nm;
    }
    for (; e < end; e++) {
        int c0 = g_scol[e];
        const float4 k0 = __ldg((const float4*)(g_K + (size_t)c0 * FD + lane * 4));
        const float4 v0 = __ldg((const float4*)(g_V + (size_t)c0 * FD + lane * 4));
        float t0 = q.x * k0.x + q.y * k0.y + q.z * k0.z + q.w * k0.w;
        t0 += __shfl_xor_sync(0xffffffffu, t0, 1);
        t0 += __shfl_xor_sync(0xffffffffu, t0, 2);
        float nm = fmaxf(m, t0);
        float f  = __expf(m - nm);
        float w0 = __expf(t0 - nm);
        s = s * f + w0;
        acc.x = acc.x * f + w0 * v0.x;
        acc.y = acc.y * f + w0 * v0.y;
        acc.z = acc.z * f + w0 * v0.z;
        acc.w = acc.w * f + w0 * v0.w;
        m = nm;
    }

    const float inv = 1.f / s;
    const float4 b4 = __ldg((const float4*)(bias + lane * 4));
    float4 o = make_float4(acc.x * inv + b4.x, acc.y * inv + b4.y,
                           acc.z * inv + b4.z, acc.w * inv + b4.w);
    *(float4*)(out + (size_t)n * FD + lane * 4) = o;
}

// -------------------- launch --------------------
extern "C" void kernel_launch(void* const* d_in, const int* in_sizes, int n_in,
                              void* d_out, int out_size)
{
    const float* x  = (const float*)d_in[0];
    const int*   ei = (const int*)d_in[1];
    const float* Wq = (const float*)d_in[2];
    const float* bq = (const float*)d_in[3];
    const float* Wk = (const float*)d_in[4];
    const float* bk = (const float*)d_in[5];
    const float* Wv = (const float*)d_in[6];
    const float* bo = (const float*)d_in[7];
    float* out = (float*)d_out;

    // 1: fused histogram + Q/K/V GEMMs
    fused_gemm_hist_kernel<<<HIST_BLOCKS + 3 * GEMM_BX, 256>>>(x, ei, Wq, bq, Wk, bk, Wv);
    // 2: exclusive scan (implicit +1 self loop)
    scan_kernel<<<1, 1024>>>();
    // 3: scatter edges into per-node lists
    scatter_kernel<<<(EP + 255) / 256, 256>>>(ei);
    // 4: fused attention + aggregation (1 warp / node); resets g_cnt
    aggregate_kernel<<<(NN * 32 + 255) / 256, 256>>>(bo, out);
}

// round 6
// speedup vs baseline: 1.7101x; 1.0175x over previous
#include <cuda_runtime.h>
#include <cuda_bf16.h>
#include <math.h>
#include <stdint.h>

#define NN 50000
#define NE 800000
#define EP (NE + NN)   // edges + self loops
#define FD 128

#define HIST_BLOCKS ((NE + 255) / 256)   // 3125
#define PREP_BLOCKS 24
#define GEMM_BX     ((NN + 127) / 128)   // 391

typedef uint32_t u32;

// -------------------- device scratch (no allocs allowed) --------------------
__device__ float g_Q[NN * FD];
__device__ float g_K[NN * FD];
__device__ float g_V[NN * FD];
__device__ int   g_cnt[NN];      // zeroed at load; re-zeroed by aggregate each replay
__device__ int   g_off[NN + 1];
__device__ int   g_cur[NN];
__device__ int   g_scol[EP];
// W transposed (N-major) + bf16-split: [mat][part(hi/lo)][n=128][kpair=64] u32
__device__ u32   g_Wt[3 * 2 * 128 * 64];

// -------------------- bf16 split helpers (RN-even) --------------------
__device__ __forceinline__ u32 f2bf(float x) {
    u32 u = __float_as_uint(x);
    return (u + 0x7FFFu + ((u >> 16) & 1u)) >> 16;
}
__device__ __forceinline__ float bf2f(u32 b) { return __uint_as_float(b << 16); }

// -------------------- kernel 1: edge histogram + W prep --------------------
__global__ __launch_bounds__(256) void hist_prep_kernel(
    const int* __restrict__ ei,
    const float* __restrict__ Wq, const float* __restrict__ Wk,
    const float* __restrict__ Wv)
{
    if (blockIdx.x < HIST_BLOCKS) {
        int e = blockIdx.x * 256 + threadIdx.x;
        if (e < NE) atomicAdd(&g_cnt[ei[e]], 1);   // target = ei[0][e]
        return;
    }
    int gid = (blockIdx.x - HIST_BLOCKS) * 256 + threadIdx.x;   // 0..6143
#pragma unroll
    for (int i = 0; i < 4; i++) {
        int P   = gid + i * 6144;            // 0..24575
        int mat = P >> 13;
        int kp  = (P >> 7) & 63;
        int n   = P & 127;                   // n fastest -> coalesced W reads
        const float* W = (mat == 0) ? Wq : ((mat == 1) ? Wk : Wv);
        float w0 = W[(2 * kp) * FD + n];
        float w1 = W[(2 * kp + 1) * FD + n];
        u32 h0 = f2bf(w0), h1 = f2bf(w1);
        u32 l0 = f2bf(w0 - bf2f(h0)), l1 = f2bf(w1 - bf2f(h1));
        g_Wt[((mat * 2 + 0) * 128 + n) * 64 + kp] = h0 | (h1 << 16);
        g_Wt[((mat * 2 + 1) * 128 + n) * 64 + kp] = l0 | (l1 << 16);
    }
}

// -------------------- HMMA GEMM: Q/K/V, 3-term bf16 split --------------------
// Per block: 128 rows x 128 cols x K=128.  8 warps, each warp m16 x n128.
// smem rows are 68 u32 (272B) -> LDS bank = (68*row + tig) mod 32, conflict-free.
#define XH 0
#define XL 8704
#define WH 17408
#define WL 26112
#define SMEM_BYTES (34816 * 4)   // 139264

__device__ __forceinline__ void mma_bf16(float* c, u32 a0, u32 a1, u32 a2, u32 a3,
                                         u32 b0, u32 b1) {
    asm volatile(
        "mma.sync.aligned.m16n8k16.row.col.f32.bf16.bf16.f32 "
        "{%0,%1,%2,%3}, {%4,%5,%6,%7}, {%8,%9}, {%0,%1,%2,%3};"
        : "+f"(c[0]), "+f"(c[1]), "+f"(c[2]), "+f"(c[3])
        : "r"(a0), "r"(a1), "r"(a2), "r"(a3), "r"(b0), "r"(b1));
}

__global__ __launch_bounds__(256) void gemm_mma_kernel(
    const float* __restrict__ x,
    const float* __restrict__ bq, const float* __restrict__ bk)
{
    extern __shared__ u32 sm[];
    const int t    = threadIdx.x;
    const int warp = t >> 5;
    const int lane = t & 31;
    const int gID  = lane >> 2;
    const int tig  = lane & 3;
    const int row0 = blockIdx.x * 128;

    // ---- stage x tile: split into bf16 hi/lo ----
    {
        int r    = t >> 1;
        int half = t & 1;
        bool rok = (row0 + r) < NN;
        const float4* xr = (const float4*)(x + (size_t)(row0 + r) * FD + half * 64);
        int base = r * 68 + half * 32;
#pragma unroll
        for (int i = 0; i < 16; i++) {
            float4 v = rok ? xr[i] : make_float4(0.f, 0.f, 0.f, 0.f);
            u32 hx = f2bf(v.x), hy = f2bf(v.y), hz = f2bf(v.z), hw = f2bf(v.w);
            u32 lx = f2bf(v.x - bf2f(hx)), ly = f2bf(v.y - bf2f(hy));
            u32 lz = f2bf(v.z - bf2f(hz)), lw = f2bf(v.w - bf2f(hw));
            sm[XH + base + 2 * i]     = hx | (hy << 16);
            sm[XH + base + 2 * i + 1] = hz | (hw << 16);
            sm[XL + base + 2 * i]     = lx | (ly << 16);
            sm[XL + base + 2 * i + 1] = lz | (lw << 16);
        }
    }

    for (int mat = 0; mat < 3; mat++) {
        // ---- stage W^T (hi/lo) for this mat ----
        {
            int part = t >> 7;
            int n    = t & 127;
            const uint4* src = (const uint4*)(g_Wt + ((mat * 2 + part) * 128 + n) * 64);
            u32* dst = sm + (part ? WL : WH) + n * 68;
#pragma unroll
            for (int j = 0; j < 16; j++)
                *(uint4*)(dst + 4 * j) = src[j];
        }
        __syncthreads();

        float acc[16][4];
#pragma unroll
        for (int nt = 0; nt < 16; nt++)
#pragma unroll
            for (int c = 0; c < 4; c++) acc[nt][c] = 0.f;

        const int mrow = warp * 16 + gID;
#pragma unroll 1
        for (int term = 0; term < 3; term++) {
            const u32 xbase = (term == 1) ? XL : XH;
            const u32 wbase = (term == 2) ? WL : WH;
#pragma unroll 2
            for (int ks = 0; ks < 8; ks++) {
                u32 a0 = sm[xbase + mrow * 68 + 8 * ks + tig];
                u32 a1 = sm[xbase + (mrow + 8) * 68 + 8 * ks + tig];
                u32 a2 = sm[xbase + mrow * 68 + 8 * ks + 4 + tig];
                u32 a3 = sm[xbase + (mrow + 8) * 68 + 8 * ks + 4 + tig];
#pragma unroll
                for (int nt = 0; nt < 16; nt++) {
                    int n = nt * 8 + gID;
                    u32 b0 = sm[wbase + n * 68 + 8 * ks + tig];
                    u32 b1 = sm[wbase + n * 68 + 8 * ks + 4 + tig];
                    mma_bf16(acc[nt], a0, a1, a2, a3, b0, b1);
                }
            }
        }

        // ---- epilogue: bias + relu + store ----
        const float* B = (mat == 0) ? bq : ((mat == 1) ? bk : nullptr);
        float* C = (mat == 0) ? g_Q : ((mat == 1) ? g_K : g_V);
        const bool dorelu = (mat < 2);
        int r0 = row0 + warp * 16 + gID;
        int r1 = r0 + 8;
#pragma unroll
        for (int nt = 0; nt < 16; nt++) {
            int col = nt * 8 + 2 * tig;
            float2 bv = B ? *(const float2*)(B + col) : make_float2(0.f, 0.f);
            float2 o0 = make_float2(acc[nt][0] + bv.x, acc[nt][1] + bv.y);
            float2 o1 = make_float2(acc[nt][2] + bv.x, acc[nt][3] + bv.y);
            if (dorelu) {
                o0.x = fmaxf(o0.x, 0.f); o0.y = fmaxf(o0.y, 0.f);
                o1.x = fmaxf(o1.x, 0.f); o1.y = fmaxf(o1.y, 0.f);
            }
            if (r0 < NN) *(float2*)(C + (size_t)r0 * FD + col) = o0;
            if (r1 < NN) *(float2*)(C + (size_t)r1 * FD + col) = o1;
        }
        __syncthreads();   // protect W smem before next mat overwrites
    }
}

// -------------------- exclusive scan over (g_cnt[i] + 1) --------------------
__global__ __launch_bounds__(1024) void scan_kernel() {
    __shared__ int sums[1024];
    const int t = threadIdx.x;
    const int CH = (NN + 1023) / 1024;   // 49
    int start = t * CH;
    int end   = start + CH; if (end > NN) end = NN;

    int s = 0;
    for (int i = start; i < end; i++) s += g_cnt[i] + 1;
    sums[t] = s;
    __syncthreads();
    for (int d = 1; d < 1024; d <<= 1) {
        int v = (t >= d) ? sums[t - d] : 0;
        __syncthreads();
        sums[t] += v;
        __syncthreads();
    }
    int run = sums[t] - s;
    for (int i = start; i < end; i++) {
        g_off[i] = run;
        g_cur[i] = run;
        run += g_cnt[i] + 1;
    }
    if (start < NN && end == NN) g_off[NN] = run;
}

__global__ void scatter_kernel(const int* __restrict__ ei) {
    int e = blockIdx.x * blockDim.x + threadIdx.x;
    if (e >= EP) return;
    int rr, cc;
    if (e < NE) { rr = ei[e]; cc = ei[NE + e]; }
    else        { rr = e - NE; cc = rr; }          // self loop
    int pos = atomicAdd(&g_cur[rr], 1);
    g_scol[pos] = cc;
}

// -------------------- fused attention + aggregation --------------------
__global__ __launch_bounds__(256) void aggregate_kernel(
    const float* __restrict__ bias, float* __restrict__ out)
{
    const int warp = (blockIdx.x * blockDim.x + threadIdx.x) >> 5;
    const int lane = threadIdx.x & 31;
    if (warp >= NN) return;
    const int n = warp;
    if (lane == 0) g_cnt[n] = 0;     // reset for next replay

    const float4 q = __ldg((const float4*)(g_Q + (size_t)n * FD + lane * 4));

    const int beg = g_off[n];
    const int end = g_off[n + 1];

    float m = -INFINITY;
    float s = 0.f;
    float4 acc = make_float4(0.f, 0.f, 0.f, 0.f);

    int e = beg;
    for (; e + 4 <= end; e += 4) {
        int c0 = g_scol[e];
        int c1 = g_scol[e + 1];
        int c2 = g_scol[e + 2];
        int c3 = g_scol[e + 3];
        const float4 k0 = __ldg((const float4*)(g_K + (size_t)c0 * FD + lane * 4));
        const float4 k1 = __ldg((const float4*)(g_K + (size_t)c1 * FD + lane * 4));
        const float4 k2 = __ldg((const float4*)(g_K + (size_t)c2 * FD + lane * 4));
        const float4 k3 = __ldg((const float4*)(g_K + (size_t)c3 * FD + lane * 4));
        const float4 v0 = __ldg((const float4*)(g_V + (size_t)c0 * FD + lane * 4));
        const float4 v1 = __ldg((const float4*)(g_V + (size_t)c1 * FD + lane * 4));
        const float4 v2 = __ldg((const float4*)(g_V + (size_t)c2 * FD + lane * 4));
        const float4 v3 = __ldg((const float4*)(g_V + (size_t)c3 * FD + lane * 4));

        float t0 = q.x * k0.x + q.y * k0.y + q.z * k0.z + q.w * k0.w;
        float t1 = q.x * k1.x + q.y * k1.y + q.z * k1.z + q.w * k1.w;
        float t2 = q.x * k2.x + q.y * k2.y + q.z * k2.z + q.w * k2.w;
        float t3 = q.x * k3.x + q.y * k3.y + q.z * k3.z + q.w * k3.w;
        t0 += __shfl_xor_sync(0xffffffffu, t0, 1);
        t1 += __shfl_xor_sync(0xffffffffu, t1, 1);
        t2 += __shfl_xor_sync(0xffffffffu, t2, 1);
        t3 += __shfl_xor_sync(0xffffffffu, t3, 1);
        t0 += __shfl_xor_sync(0xffffffffu, t0, 2);
        t1 += __shfl_xor_sync(0xffffffffu, t1, 2);
        t2 += __shfl_xor_sync(0xffffffffu, t2, 2);
        t3 += __shfl_xor_sync(0xffffffffu, t3, 2);

        float nm = fmaxf(fmaxf(m, fmaxf(t0, t1)), fmaxf(t2, t3));
        float f  = __expf(m - nm);
        float w0 = __expf(t0 - nm);
        float w1 = __expf(t1 - nm);
        float w2 = __expf(t2 - nm);
        float w3 = __expf(t3 - nm);
        s = s * f + ((w0 + w1) + (w2 + w3));
        acc.x = acc.x * f + ((w0 * v0.x + w1 * v1.x) + (w2 * v2.x + w3 * v3.x));
        acc.y = acc.y * f + ((w0 * v0.y + w1 * v1.y) + (w2 * v2.y + w3 * v3.y));
        acc.z = acc.z * f + ((w0 * v0.z + w1 * v1.z) + (w2 * v2.z + w3 * v3.z));
        acc.w = acc.w * f + ((w0 * v0.w + w1 * v1.w) + (w2 * v2.w + w3 * v3.w));
        m = nm;
    }
    for (; e < end; e++) {
        int c0 = g_scol[e];
        const float4 k0 = __ldg((const float4*)(g_K + (size_t)c0 * FD + lane * 4));
        const float4 v0 = __ldg((const float4*)(g_V + (size_t)c0 * FD + lane * 4));
        float t0 = q.x * k0.x + q.y * k0.y + q.z * k0.z + q.w * k0.w;
        t0 += __shfl_xor_sync(0xffffffffu, t0, 1);
        t0 += __shfl_xor_sync(0xffffffffu, t0, 2);
        float nm = fmaxf(m, t0);
        float f  = __expf(m - nm);
        float w0 = __expf(t0 - nm);
        s = s * f + w0;
        acc.x = acc.x * f + w0 * v0.x;
        acc.y = acc.y * f + w0 * v0.y;
        acc.z = acc.z * f + w0 * v0.z;
        acc.w = acc.w * f + w0 * v0.w;
        m = nm;
    }

    const float inv = 1.f / s;
    const float4 b4 = __ldg((const float4*)(bias + lane * 4));
    float4 o = make_float4(acc.x * inv + b4.x, acc.y * inv + b4.y,
                           acc.z * inv + b4.z, acc.w * inv + b4.w);
    *(float4*)(out + (size_t)n * FD + lane * 4) = o;
}

// -------------------- launch --------------------
extern "C" void kernel_launch(void* const* d_in, const int* in_sizes, int n_in,
                              void* d_out, int out_size)
{
    const float* x  = (const float*)d_in[0];
    const int*   ei = (const int*)d_in[1];
    const float* Wq = (const float*)d_in[2];
    const float* bq = (const float*)d_in[3];
    const float* Wk = (const float*)d_in[4];
    const float* bk = (const float*)d_in[5];
    const float* Wv = (const float*)d_in[6];
    const float* bo = (const float*)d_in[7];
    float* out = (float*)d_out;

    static int smem_set = 0;
    if (!smem_set) {
        cudaFuncSetAttribute(gemm_mma_kernel,
                             cudaFuncAttributeMaxDynamicSharedMemorySize, SMEM_BYTES);
        smem_set = 1;
    }

    // 1: edge histogram + W transpose/split prep
    hist_prep_kernel<<<HIST_BLOCKS + PREP_BLOCKS, 256>>>(ei, Wq, Wk, Wv);
    // 2: exclusive scan (implicit +1 self loop)
    scan_kernel<<<1, 1024>>>();
    // 3: scatter edges into per-node lists
    scatter_kernel<<<(EP + 255) / 256, 256>>>(ei);
    // 4: HMMA Q/K/V GEMM (ncu capture slot)
    gemm_mma_kernel<<<GEMM_BX, 256, SMEM_BYTES>>>(x, bq, bk);
    // 5: fused attention + aggregation; resets g_cnt
    aggregate_kernel<<<(NN * 32 + 255) / 256, 256>>>(bo, out);
}

// round 7
// speedup vs baseline: 1.8825x; 1.1008x over previous
#include <cuda_runtime.h>
#include <cuda_bf16.h>
#include <math.h>
#include <stdint.h>

#define NN 50000
#define NE 800000
#define EP (NE + NN)   // edges + self loops
#define FD 128

#define HIST_BLOCKS ((NE + 255) / 256)   // 3125
#define PREP_BLOCKS 24
#define GEMM_BX     ((NN + 127) / 128)   // 391

typedef uint32_t u32;

// -------------------- device scratch (no allocs allowed) --------------------
__device__ float g_Q[NN * FD];
__device__ float g_K[NN * FD];
__device__ float g_V[NN * FD];
__device__ int   g_cnt[NN];      // zeroed at load; re-zeroed by aggregate each replay
__device__ int   g_off[NN + 1];
__device__ int   g_cur[NN];
__device__ int   g_scol[EP];
// W transposed (N-major) + bf16-split: [mat][part(hi/lo)][n=128][kpair=64] u32
__device__ u32   g_Wt[3 * 2 * 128 * 64];

// -------------------- bf16 split helpers (RN-even) --------------------
__device__ __forceinline__ u32 f2bf(float x) {
    u32 u = __float_as_uint(x);
    return (u + 0x7FFFu + ((u >> 16) & 1u)) >> 16;
}
__device__ __forceinline__ float bf2f(u32 b) { return __uint_as_float(b << 16); }

__device__ __forceinline__ u32 smem_u32(const void* p) {
    u32 a; asm("{ .reg .u64 t; cvta.to.shared.u64 t, %1; cvt.u32.u64 %0, t; }"
               : "=r"(a) : "l"(p));
    return a;
}

// -------------------- kernel 1: edge histogram + W prep --------------------
__global__ __launch_bounds__(256) void hist_prep_kernel(
    const int* __restrict__ ei,
    const float* __restrict__ Wq, const float* __restrict__ Wk,
    const float* __restrict__ Wv)
{
    if (blockIdx.x < HIST_BLOCKS) {
        int e = blockIdx.x * 256 + threadIdx.x;
        if (e < NE) atomicAdd(&g_cnt[ei[e]], 1);   // target = ei[0][e]
        return;
    }
    int gid = (blockIdx.x - HIST_BLOCKS) * 256 + threadIdx.x;   // 0..6143
#pragma unroll
    for (int i = 0; i < 4; i++) {
        int P   = gid + i * 6144;            // 0..24575
        int mat = P >> 13;
        int kp  = (P >> 7) & 63;
        int n   = P & 127;                   // n fastest -> coalesced W reads
        const float* W = (mat == 0) ? Wq : ((mat == 1) ? Wk : Wv);
        float w0 = W[(2 * kp) * FD + n];
        float w1 = W[(2 * kp + 1) * FD + n];
        u32 h0 = f2bf(w0), h1 = f2bf(w1);
        u32 l0 = f2bf(w0 - bf2f(h0)), l1 = f2bf(w1 - bf2f(h1));
        g_Wt[((mat * 2 + 0) * 128 + n) * 64 + kp] = h0 | (h1 << 16);
        g_Wt[((mat * 2 + 1) * 128 + n) * 64 + kp] = l0 | (l1 << 16);
    }
}

// -------------------- HMMA GEMM: Q/K/V, 3-term bf16 split, LDSM --------------
// Per block: 128 rows x 128 cols x K=128.  8 warps, each warp m16 x n128.
// smem rows: 68 u32 (272B) -> every 8-row LDSM tile starts at banks
// {0,4,...,28}+c, covering all 32 banks: conflict-free.
#define XH 0
#define XL 8704
#define WH 17408
#define WL 26112
#define SMEM_BYTES (34816 * 4)   // 139264

__device__ __forceinline__ void mma_bf16(float* c, const u32* a, u32 b0, u32 b1) {
    asm volatile(
        "mma.sync.aligned.m16n8k16.row.col.f32.bf16.bf16.f32 "
        "{%0,%1,%2,%3}, {%4,%5,%6,%7}, {%8,%9}, {%0,%1,%2,%3};"
        : "+f"(c[0]), "+f"(c[1]), "+f"(c[2]), "+f"(c[3])
        : "r"(a[0]), "r"(a[1]), "r"(a[2]), "r"(a[3]), "r"(b0), "r"(b1));
}
__device__ __forceinline__ void ldsm4(u32* r, u32 addr) {
    asm volatile("ldmatrix.sync.aligned.m8n8.x4.shared.b16 {%0,%1,%2,%3}, [%4];"
        : "=r"(r[0]), "=r"(r[1]), "=r"(r[2]), "=r"(r[3]) : "r"(addr));
}

__global__ __launch_bounds__(256) void gemm_mma_kernel(
    const float* __restrict__ x,
    const float* __restrict__ bq, const float* __restrict__ bk)
{
    extern __shared__ u32 sm[];
    const u32 sb   = smem_u32(sm);
    const int t    = threadIdx.x;
    const int warp = t >> 5;
    const int lane = t & 31;
    const int gID  = lane >> 2;
    const int tig  = lane & 3;
    const int row0 = blockIdx.x * 128;

    // ---- stage x tile: split into bf16 hi/lo ----
    {
        int r    = t >> 1;
        int half = t & 1;
        bool rok = (row0 + r) < NN;
        const float4* xr = (const float4*)(x + (size_t)(row0 + r) * FD + half * 64);
        int base = r * 68 + half * 32;
#pragma unroll
        for (int i = 0; i < 16; i++) {
            float4 v = rok ? xr[i] : make_float4(0.f, 0.f, 0.f, 0.f);
            u32 hx = f2bf(v.x), hy = f2bf(v.y), hz = f2bf(v.z), hw = f2bf(v.w);
            u32 lx = f2bf(v.x - bf2f(hx)), ly = f2bf(v.y - bf2f(hy));
            u32 lz = f2bf(v.z - bf2f(hz)), lw = f2bf(v.w - bf2f(hw));
            sm[XH + base + 2 * i]     = hx | (hy << 16);
            sm[XH + base + 2 * i + 1] = hz | (hw << 16);
            sm[XL + base + 2 * i]     = lx | (ly << 16);
            sm[XL + base + 2 * i + 1] = lz | (lw << 16);
        }
    }

    // LDSM per-thread row/col mapping
    // A tiles: (m0-7,k0-7) (m8-15,k0-7) (m0-7,k8-15) (m8-15,k8-15)
    const int aRow = warp * 16 + (lane & 7) + 8 * ((lane >> 3) & 1);
    const u32 aColB = 16u * (lane >> 4);              // bytes: +4 u32 for k8-15
    // B tiles: (n-lo,k0-7) (n-lo,k8-15) (n-hi,k0-7) (n-hi,k8-15)
    const int bRow = (lane & 7) + 8 * (lane >> 4);
    const u32 bColB = 16u * ((lane >> 3) & 1);

    for (int mat = 0; mat < 3; mat++) {
        // ---- stage W^T (hi/lo) for this mat ----
        {
            int part = t >> 7;
            int n    = t & 127;
            const uint4* src = (const uint4*)(g_Wt + ((mat * 2 + part) * 128 + n) * 64);
            u32* dst = sm + (part ? WL : WH) + n * 68;
#pragma unroll
            for (int j = 0; j < 16; j++)
                *(uint4*)(dst + 4 * j) = src[j];
        }
        __syncthreads();

        float acc[16][4];
#pragma unroll
        for (int nt = 0; nt < 16; nt++)
#pragma unroll
            for (int c = 0; c < 4; c++) acc[nt][c] = 0.f;

#pragma unroll 1
        for (int term = 0; term < 3; term++) {
            const u32 xb = (term == 1) ? XL : XH;
            const u32 wb = (term == 2) ? WL : WH;
            const u32 aBase = sb + 4u * (xb + (u32)aRow * 68u) + aColB;
            const u32 bBase = sb + 4u * (wb + (u32)bRow * 68u) + bColB;
#pragma unroll
            for (int ks = 0; ks < 8; ks++) {
                u32 a[4];
                ldsm4(a, aBase + 32u * ks);
#pragma unroll
                for (int j = 0; j < 8; j++) {
                    u32 b[4];
                    ldsm4(b, bBase + 4u * (16u * j * 68u) + 32u * ks);
                    mma_bf16(acc[2 * j],     a, b[0], b[1]);
                    mma_bf16(acc[2 * j + 1], a, b[2], b[3]);
                }
            }
        }

        // ---- epilogue: bias + relu + store ----
        const float* B = (mat == 0) ? bq : ((mat == 1) ? bk : nullptr);
        float* C = (mat == 0) ? g_Q : ((mat == 1) ? g_K : g_V);
        const bool dorelu = (mat < 2);
        int r0 = row0 + warp * 16 + gID;
        int r1 = r0 + 8;
#pragma unroll
        for (int nt = 0; nt < 16; nt++) {
            int col = nt * 8 + 2 * tig;
            float2 bv = B ? *(const float2*)(B + col) : make_float2(0.f, 0.f);
            float2 o0 = make_float2(acc[nt][0] + bv.x, acc[nt][1] + bv.y);
            float2 o1 = make_float2(acc[nt][2] + bv.x, acc[nt][3] + bv.y);
            if (dorelu) {
                o0.x = fmaxf(o0.x, 0.f); o0.y = fmaxf(o0.y, 0.f);
                o1.x = fmaxf(o1.x, 0.f); o1.y = fmaxf(o1.y, 0.f);
            }
            if (r0 < NN) *(float2*)(C + (size_t)r0 * FD + col) = o0;
            if (r1 < NN) *(float2*)(C + (size_t)r1 * FD + col) = o1;
        }
        __syncthreads();   // protect W smem before next mat overwrites
    }
}

// -------------------- exclusive scan over (g_cnt[i] + 1) --------------------
__global__ __launch_bounds__(1024) void scan_kernel() {
    __shared__ int sums[1024];
    const int t = threadIdx.x;
    const int CH = (NN + 1023) / 1024;   // 49
    int start = t * CH;
    int end   = start + CH; if (end > NN) end = NN;

    int s = 0;
    for (int i = start; i < end; i++) s += g_cnt[i] + 1;
    sums[t] = s;
    __syncthreads();
    for (int d = 1; d < 1024; d <<= 1) {
        int v = (t >= d) ? sums[t - d] : 0;
        __syncthreads();
        sums[t] += v;
        __syncthreads();
    }
    int run = sums[t] - s;
    for (int i = start; i < end; i++) {
        g_off[i] = run;
        g_cur[i] = run;
        run += g_cnt[i] + 1;
    }
    if (start < NN && end == NN) g_off[NN] = run;
}

__global__ void scatter_kernel(const int* __restrict__ ei) {
    int e = blockIdx.x * blockDim.x + threadIdx.x;
    if (e >= EP) return;
    int rr, cc;
    if (e < NE) { rr = ei[e]; cc = ei[NE + e]; }
    else        { rr = e - NE; cc = rr; }          // self loop
    int pos = atomicAdd(&g_cur[rr], 1);
    g_scol[pos] = cc;
}

// -------------------- fused attention + aggregation --------------------
__global__ __launch_bounds__(256) void aggregate_kernel(
    const float* __restrict__ bias, float* __restrict__ out)
{
    const int warp = (blockIdx.x * blockDim.x + threadIdx.x) >> 5;
    const int lane = threadIdx.x & 31;
    if (warp >= NN) return;
    const int n = warp;
    if (lane == 0) g_cnt[n] = 0;     // reset for next replay

    const float4 q = __ldg((const float4*)(g_Q + (size_t)n * FD + lane * 4));

    const int beg = g_off[n];
    const int end = g_off[n + 1];

    float m = -INFINITY;
    float s = 0.f;
    float4 acc = make_float4(0.f, 0.f, 0.f, 0.f);

    int e = beg;
    for (; e + 4 <= end; e += 4) {
        int c0 = g_scol[e];
        int c1 = g_scol[e + 1];
        int c2 = g_scol[e + 2];
        int c3 = g_scol[e + 3];
        const float4 k0 = __ldg((const float4*)(g_K + (size_t)c0 * FD + lane * 4));
        const float4 k1 = __ldg((const float4*)(g_K + (size_t)c1 * FD + lane * 4));
        const float4 k2 = __ldg((const float4*)(g_K + (size_t)c2 * FD + lane * 4));
        const float4 k3 = __ldg((const float4*)(g_K + (size_t)c3 * FD + lane * 4));
        const float4 v0 = __ldg((const float4*)(g_V + (size_t)c0 * FD + lane * 4));
        const float4 v1 = __ldg((const float4*)(g_V + (size_t)c1 * FD + lane * 4));
        const float4 v2 = __ldg((const float4*)(g_V + (size_t)c2 * FD + lane * 4));
        const float4 v3 = __ldg((const float4*)(g_V + (size_t)c3 * FD + lane * 4));

        float t0 = q.x * k0.x + q.y * k0.y + q.z * k0.z + q.w * k0.w;
        float t1 = q.x * k1.x + q.y * k1.y + q.z * k1.z + q.w * k1.w;
        float t2 = q.x * k2.x + q.y * k2.y + q.z * k2.z + q.w * k2.w;
        float t3 = q.x * k3.x + q.y * k3.y + q.z * k3.z + q.w * k3.w;
        t0 += __shfl_xor_sync(0xffffffffu, t0, 1);
        t1 += __shfl_xor_sync(0xffffffffu, t1, 1);
        t2 += __shfl_xor_sync(0xffffffffu, t2, 1);
        t3 += __shfl_xor_sync(0xffffffffu, t3, 1);
        t0 += __shfl_xor_sync(0xffffffffu, t0, 2);
        t1 += __shfl_xor_sync(0xffffffffu, t1, 2);
        t2 += __shfl_xor_sync(0xffffffffu, t2, 2);
        t3 += __shfl_xor_sync(0xffffffffu, t3, 2);

        float nm = fmaxf(fmaxf(m, fmaxf(t0, t1)), fmaxf(t2, t3));
        float f  = __expf(m - nm);
        float w0 = __expf(t0 - nm);
        float w1 = __expf(t1 - nm);
        float w2 = __expf(t2 - nm);
        float w3 = __expf(t3 - nm);
        s = s * f + ((w0 + w1) + (w2 + w3));
        acc.x = acc.x * f + ((w0 * v0.x + w1 * v1.x) + (w2 * v2.x + w3 * v3.x));
        acc.y = acc.y * f + ((w0 * v0.y + w1 * v1.y) + (w2 * v2.y + w3 * v3.y));
        acc.z = acc.z * f + ((w0 * v0.z + w1 * v1.z) + (w2 * v2.z + w3 * v3.z));
        acc.w = acc.w * f + ((w0 * v0.w + w1 * v1.w) + (w2 * v2.w + w3 * v3.w));
        m = nm;
    }
    for (; e < end; e++) {
        int c0 = g_scol[e];
        const float4 k0 = __ldg((const float4*)(g_K + (size_t)c0 * FD + lane * 4));
        const float4 v0 = __ldg((const float4*)(g_V + (size_t)c0 * FD + lane * 4));
        float t0 = q.x * k0.x + q.y * k0.y + q.z * k0.z + q.w * k0.w;
        t0 += __shfl_xor_sync(0xffffffffu, t0, 1);
        t0 += __shfl_xor_sync(0xffffffffu, t0, 2);
        float nm = fmaxf(m, t0);
        float f  = __expf(m - nm);
        float w0 = __expf(t0 - nm);
        s = s * f + w0;
        acc.x = acc.x * f + w0 * v0.x;
        acc.y = acc.y * f + w0 * v0.y;
        acc.z = acc.z * f + w0 * v0.z;
        acc.w = acc.w * f + w0 * v0.w;
        m = nm;
    }

    const float inv = 1.f / s;
    const float4 b4 = __ldg((const float4*)(bias + lane * 4));
    float4 o = make_float4(acc.x * inv + b4.x, acc.y * inv + b4.y,
                           acc.z * inv + b4.z, acc.w * inv + b4.w);
    *(float4*)(out + (size_t)n * FD + lane * 4) = o;
}

// -------------------- launch --------------------
extern "C" void kernel_launch(void* const* d_in, const int* in_sizes, int n_in,
                              void* d_out, int out_size)
{
    const float* x  = (const float*)d_in[0];
    const int*   ei = (const int*)d_in[1];
    const float* Wq = (const float*)d_in[2];
    const float* bq = (const float*)d_in[3];
    const float* Wk = (const float*)d_in[4];
    const float* bk = (const float*)d_in[5];
    const float* Wv = (const float*)d_in[6];
    const float* bo = (const float*)d_in[7];
    float* out = (float*)d_out;

    static int smem_set = 0;
    if (!smem_set) {
        cudaFuncSetAttribute(gemm_mma_kernel,
                             cudaFuncAttributeMaxDynamicSharedMemorySize, SMEM_BYTES);
        smem_set = 1;
    }

    // 1: edge histogram + W transpose/split prep
    hist_prep_kernel<<<HIST_BLOCKS + PREP_BLOCKS, 256>>>(ei, Wq, Wk, Wv);
    // 2: exclusive scan (implicit +1 self loop)
    scan_kernel<<<1, 1024>>>();
    // 3: scatter edges into per-node lists
    scatter_kernel<<<(EP + 255) / 256, 256>>>(ei);
    // 4: HMMA Q/K/V GEMM (ncu capture slot)
    gemm_mma_kernel<<<GEMM_BX, 256, SMEM_BYTES>>>(x, bq, bk);
    // 5: fused attention + aggregation; resets g_cnt
    aggregate_kernel<<<(NN * 32 + 255) / 256, 256>>>(bo, out);
}